// round 16
// baseline (speedup 1.0000x reference)
#include <cuda_runtime.h>
#include <cuda_bf16.h>
#include <math.h>

// Problem constants (fixed-shape problem)
#define NMAX 50048
#define EMAX 800000

// ---------------- device scratch (no allocations allowed) ----------------
__device__ int    g_cnt[NMAX];
__device__ int    g_rowptr[NMAX + 2];
__device__ int    g_wcur[NMAX];
__device__ int    g_eid[EMAX];
__device__ float4 g_wp[EMAX];          // normalized (w0,w1,w2,0) in CSR order
__device__ float  g_ssum0[NMAX];       // after scan: holds 1/sum (or 0)
__device__ float  g_ssum1[NMAX];
__device__ float  g_ssum2[NMAX];
__device__ float  g_agg[50000 * 384];
__device__ float  g_c[50000 * 384];
__device__ float  g_ctx[50000 * 128];
__device__ float  g_h[50000 * 128];
__device__ int    g_cflag[64];         // chunk total + 1 (0 = not ready)

// ---------------- small helpers ----------------
__device__ __forceinline__ unsigned f2tf(float x) {
    unsigned r;
    asm("cvt.rna.tf32.f32 %0, %1;" : "=r"(r) : "f"(x));
    return r;
}
__device__ __forceinline__ unsigned s2u(const void* p) {
    unsigned r;
    asm("{ .reg .u64 t; cvta.to.shared.u64 t, %1; cvt.u32.u64 %0, t; }"
        : "=r"(r) : "l"(p));
    return r;
}
#define CP16(dst, src, sz) \
    asm volatile("cp.async.cg.shared.global [%0], [%1], 16, %2;" \
                 :: "r"(dst), "l"(src), "r"(sz))
#define CPCOMMIT() asm volatile("cp.async.commit_group;")
#define CPWAIT(n)  asm volatile("cp.async.wait_group %0;" :: "n"(n))
#define MMA_TF32(acc, a0, a1, a2, a3, b0, b1) \
    asm volatile( \
        "mma.sync.aligned.m16n8k8.row.col.f32.tf32.tf32.f32 " \
        "{%0,%1,%2,%3}, {%4,%5,%6,%7}, {%8,%9}, {%0,%1,%2,%3};" \
        : "+f"((acc)[0]), "+f"((acc)[1]), "+f"((acc)[2]), "+f"((acc)[3]) \
        : "r"(a0), "r"(a1), "r"(a2), "r"(a3), "r"(b0), "r"(b1))

// ---------------- init ----------------
__global__ void k_init(int N) {
    int i = blockIdx.x * blockDim.x + threadIdx.x;
    if (i < N) {
        g_cnt[i] = 0;
        g_ssum0[i] = 0.f; g_ssum1[i] = 0.f; g_ssum2[i] = 0.f;
    }
    if (i < 64) g_cflag[i] = 0;
}

// ---------------- edge pass 1: histogram + exp-sums ----------------
__global__ void k_edge1(const int* __restrict__ dst,
                        const float* __restrict__ l1,
                        const float* __restrict__ l2,
                        const float* __restrict__ l3, int E) {
    int e = blockIdx.x * blockDim.x + threadIdx.x;
    if (e >= E) return;
    int d = dst[e];
    atomicAdd(&g_cnt[d], 1);
    atomicAdd(&g_ssum0[d], __expf(l1[e]));
    atomicAdd(&g_ssum1[d], __expf(l2[e]));
    atomicAdd(&g_ssum2[d], __expf(l3[e]));
}

// ---------------- fused scan: local prefix + decoupled chunk offsets ---------
// 49 blocks, all co-resident (<=148 SMs): each publishes its chunk total
// (value+1, single atomic word) BEFORE spinning on lower-indexed blocks,
// so the wait chain is acyclic and deadlock-free.
__global__ void k_scan(int N, int E) {
    __shared__ int sh[1024];
    __shared__ int off_sh;
    int t = threadIdx.x;
    int bid = blockIdx.x;
    int n = bid * 1024 + t;
    int v = (n < N) ? g_cnt[n] : 0;
    sh[t] = v;
    __syncthreads();
#pragma unroll
    for (int off = 1; off < 1024; off <<= 1) {
        int x = (t >= off) ? sh[t - off] : 0;
        __syncthreads();
        sh[t] += x;
        __syncthreads();
    }
    // publish this chunk's total (value+1; 0 means not ready)
    if (t == 1023) atomicExch(&g_cflag[bid], sh[1023] + 1);
    // accumulate lower chunk totals
    if (t == 0) {
        int run = 0;
        for (int i = 0; i < bid; i++) {
            int f;
            do { f = atomicAdd(&g_cflag[i], 0); } while (f == 0);
            run += f - 1;
        }
        off_sh = run;
    }
    __syncthreads();
    if (n < N) {
        int r = sh[t] - v + off_sh;     // exclusive global prefix
        g_rowptr[n] = r;
        g_wcur[n] = r;
        float s0 = g_ssum0[n]; g_ssum0[n] = (s0 > 0.f) ? 1.f / s0 : 0.f;
        float s1 = g_ssum1[n]; g_ssum1[n] = (s1 > 0.f) ? 1.f / s1 : 0.f;
        float s2 = g_ssum2[n]; g_ssum2[n] = (s2 > 0.f) ? 1.f / s2 : 0.f;
    }
    if (n == 0) g_rowptr[N] = E;
}

// ---------------- edge pass 2: scatter edge ids + normalized packed weights ----
__global__ void k_edge2(const int* __restrict__ dst,
                        const float* __restrict__ l1,
                        const float* __restrict__ l2,
                        const float* __restrict__ l3, int E) {
    int e = blockIdx.x * blockDim.x + threadIdx.x;
    if (e >= E) return;
    int d = dst[e];
    int p = atomicAdd(&g_wcur[d], 1);
    g_eid[p] = e;
    float4 w;
    w.x = __expf(l1[e]) * g_ssum0[d];
    w.y = __expf(l2[e]) * g_ssum1[d];
    w.z = __expf(l3[e]) * g_ssum2[d];
    w.w = 0.f;
    g_wp[p] = w;
}

// ---------------- gather: agg_i[n] = sum_e a_i(e) * ef_i[e] ----------------
__global__ void k_gather(const float4* __restrict__ ef1,
                         const float4* __restrict__ ef2,
                         const float4* __restrict__ ef3, int N) {
    int warp = blockIdx.x * 8 + (threadIdx.x >> 5);
    int lane = threadIdx.x & 31;
    if (warp >= N) return;
    int s = g_rowptr[warp];
    int eend = g_rowptr[warp + 1];
    float4 a0 = {0, 0, 0, 0}, a1 = {0, 0, 0, 0}, a2 = {0, 0, 0, 0};
    int k = s;
    for (; k + 4 <= eend; k += 4) {
        int e0 = g_eid[k], e1 = g_eid[k + 1], e2 = g_eid[k + 2], e3 = g_eid[k + 3];
        float4 wA = g_wp[k], wB = g_wp[k + 1], wC = g_wp[k + 2], wD = g_wp[k + 3];
        float4 u0 = ef1[e0 * 32 + lane], u1 = ef1[e1 * 32 + lane];
        float4 u2 = ef1[e2 * 32 + lane], u3 = ef1[e3 * 32 + lane];
        float4 v0 = ef2[e0 * 32 + lane], v1 = ef2[e1 * 32 + lane];
        float4 v2 = ef2[e2 * 32 + lane], v3 = ef2[e3 * 32 + lane];
        float4 x0 = ef3[e0 * 32 + lane], x1 = ef3[e1 * 32 + lane];
        float4 x2 = ef3[e2 * 32 + lane], x3 = ef3[e3 * 32 + lane];
        a0.x += wA.x * u0.x + wB.x * u1.x + wC.x * u2.x + wD.x * u3.x;
        a0.y += wA.x * u0.y + wB.x * u1.y + wC.x * u2.y + wD.x * u3.y;
        a0.z += wA.x * u0.z + wB.x * u1.z + wC.x * u2.z + wD.x * u3.z;
        a0.w += wA.x * u0.w + wB.x * u1.w + wC.x * u2.w + wD.x * u3.w;
        a1.x += wA.y * v0.x + wB.y * v1.x + wC.y * v2.x + wD.y * v3.x;
        a1.y += wA.y * v0.y + wB.y * v1.y + wC.y * v2.y + wD.y * v3.y;
        a1.z += wA.y * v0.z + wB.y * v1.z + wC.y * v2.z + wD.y * v3.z;
        a1.w += wA.y * v0.w + wB.y * v1.w + wC.y * v2.w + wD.y * v3.w;
        a2.x += wA.z * x0.x + wB.z * x1.x + wC.z * x2.x + wD.z * x3.x;
        a2.y += wA.z * x0.y + wB.z * x1.y + wC.z * x2.y + wD.z * x3.y;
        a2.z += wA.z * x0.z + wB.z * x1.z + wC.z * x2.z + wD.z * x3.z;
        a2.w += wA.z * x0.w + wB.z * x1.w + wC.z * x2.w + wD.z * x3.w;
    }
    for (; k < eend; k++) {
        int e = g_eid[k];
        float4 w = g_wp[k];
        float4 u = ef1[e * 32 + lane];
        float4 v = ef2[e * 32 + lane];
        float4 x = ef3[e * 32 + lane];
        a0.x += w.x * u.x; a0.y += w.x * u.y; a0.z += w.x * u.z; a0.w += w.x * u.w;
        a1.x += w.y * v.x; a1.y += w.y * v.y; a1.z += w.y * v.z; a1.w += w.y * v.w;
        a2.x += w.z * x.x; a2.y += w.z * x.y; a2.z += w.z * x.z; a2.w += w.z * x.w;
    }
    float4* out = reinterpret_cast<float4*>(g_agg) + warp * 96;
    out[lane]      = a0;
    out[32 + lane] = a1;
    out[64 + lane] = a2;
}

// ---------------- TF32 tensor-core GEMM (cp.async 3-stage pipelined) ----------------
struct TriC { const float* p0; const float* p1; const float* p2; };
struct TriO { float* p0; float* p1; float* p2; };
__device__ __forceinline__ const float* sel(const TriC& t, int z) {
    return z == 0 ? t.p0 : (z == 1 ? t.p1 : t.p2);
}
__device__ __forceinline__ float* sel(const TriO& t, int z) {
    return z == 0 ? t.p0 : (z == 1 ? t.p1 : t.p2);
}

#define GEMM_ASZ (128 * 36)
#define GEMM_BSZ (32 * 136)
#define GEMM_STAGE (GEMM_ASZ + GEMM_BSZ)
#define GEMM_SMEM (3 * GEMM_STAGE * 4)

template <int KTOT, int EPI, bool CONCAT3>
__global__ __launch_bounds__(256, 2)
void gemm_tc(TriC a0t, const float* __restrict__ A1, const float* __restrict__ A2,
             int lda, TriC bt, int ldb, TriC biast, TriC flagt,
             TriO ct, int ldc, int M) {
    extern __shared__ float smem[];
    const int z = blockIdx.z;
    const float* __restrict__ A0 = sel(a0t, z);
    const float* __restrict__ B = sel(bt, z);
    const float* __restrict__ bias = sel(biast, z);
    const float* __restrict__ flag_s = sel(flagt, z);
    float* __restrict__ C = sel(ct, z);

    const int t = threadIdx.x;
    const int lane = t & 31;
    const int warp = t >> 5;
    const int warpM = warp >> 1;
    const int warpN = warp & 1;
    const int row0 = blockIdx.x * 128;
    const int coff = blockIdx.y * 128;

    float acc[2][8][4];
#pragma unroll
    for (int i = 0; i < 2; i++)
#pragma unroll
        for (int j = 0; j < 8; j++)
#pragma unroll
            for (int q = 0; q < 4; q++) acc[i][j][q] = 0.f;

    const int ar = lane >> 2, ac = lane & 3;
    const int bk = lane & 3, bn = lane >> 2;
    const int NKB = KTOT / 32;

    auto issue_tile = [&](int kb) {
        float* stage = smem + (kb % 3) * GEMM_STAGE;
        float* As = stage;
        float* Bs = stage + GEMM_ASZ;
        int k0 = kb * 32;
#pragma unroll
        for (int i = 0; i < 4; i++) {
            int lin = t + i * 256;
            int r = lin >> 3;
            int kk = (lin & 7) << 2;
            int grow = row0 + r;
            bool ok = grow < M;
            const float* src;
            int kg = k0 + kk;
            if (CONCAT3) {
                const float* Ap = (kg < 128) ? A0 : ((kg < 256) ? A1 : A2);
                src = ok ? (Ap + grow * 128 + (kg & 127)) : A0;
            } else {
                src = ok ? (A0 + grow * lda + kg) : A0;
            }
            CP16(s2u(As + r * 36 + kk), src, ok ? 16 : 0);
        }
#pragma unroll
        for (int i = 0; i < 4; i++) {
            int lin = t + i * 256;
            int kr = lin >> 5;
            int nn = (lin & 31) << 2;
            CP16(s2u(Bs + kr * 136 + nn), B + (k0 + kr) * ldb + coff + nn, 16);
        }
    };

    issue_tile(0); CPCOMMIT();
    if (NKB > 1) { issue_tile(1); CPCOMMIT(); }

    for (int kb = 0; kb < NKB; kb++) {
        if (kb + 1 < NKB) { CPWAIT(1); } else { CPWAIT(0); }
        __syncthreads();
        if (kb + 2 < NKB) { issue_tile(kb + 2); CPCOMMIT(); }

        float* stage = smem + (kb % 3) * GEMM_STAGE;
        float* As = stage;
        float* Bs = stage + GEMM_ASZ;
#pragma unroll
        for (int kk = 0; kk < 32; kk += 8) {
            unsigned af[2][4];
#pragma unroll
            for (int mi = 0; mi < 2; mi++) {
                int rb = warpM * 32 + mi * 16;
                af[mi][0] = f2tf(As[(rb + ar) * 36 + kk + ac]);
                af[mi][1] = f2tf(As[(rb + ar + 8) * 36 + kk + ac]);
                af[mi][2] = f2tf(As[(rb + ar) * 36 + kk + ac + 4]);
                af[mi][3] = f2tf(As[(rb + ar + 8) * 36 + kk + ac + 4]);
            }
            unsigned bf[8][2];
#pragma unroll
            for (int ni = 0; ni < 8; ni++) {
                int nb = warpN * 64 + ni * 8;
                bf[ni][0] = f2tf(Bs[(kk + bk) * 136 + nb + bn]);
                bf[ni][1] = f2tf(Bs[(kk + bk + 4) * 136 + nb + bn]);
            }
#pragma unroll
            for (int mi = 0; mi < 2; mi++)
#pragma unroll
                for (int ni = 0; ni < 8; ni++)
                    MMA_TF32(acc[mi][ni], af[mi][0], af[mi][1], af[mi][2],
                             af[mi][3], bf[ni][0], bf[ni][1]);
        }
    }

#pragma unroll
    for (int mi = 0; mi < 2; mi++) {
        int rA = row0 + warpM * 32 + mi * 16 + (lane >> 2);
        int rB = rA + 8;
        float flA = 1.f, flB = 1.f;
        if (EPI == 1) {
            flA = (rA < M && flag_s[rA] > 0.f) ? 1.f : 0.f;
            flB = (rB < M && flag_s[rB] > 0.f) ? 1.f : 0.f;
        }
#pragma unroll
        for (int ni = 0; ni < 8; ni++) {
            int col = coff + warpN * 64 + ni * 8 + (lane & 3) * 2;
            float b0 = bias[col], b1 = bias[col + 1];
            if (rA < M) {
                float v0, v1;
                if (EPI == 1) {
                    v0 = acc[mi][ni][0] + b0 * flA;
                    v1 = acc[mi][ni][1] + b1 * flA;
                    v0 = (v0 > 0.f) ? v0 : expm1f(v0);
                    v1 = (v1 > 0.f) ? v1 : expm1f(v1);
                } else {
                    v0 = acc[mi][ni][0] + b0;
                    v1 = acc[mi][ni][1] + b1;
                }
                *reinterpret_cast<float2*>(&C[rA * ldc + col]) = make_float2(v0, v1);
            }
            if (rB < M) {
                float v2, v3;
                if (EPI == 1) {
                    v2 = acc[mi][ni][2] + b0 * flB;
                    v3 = acc[mi][ni][3] + b1 * flB;
                    v2 = (v2 > 0.f) ? v2 : expm1f(v2);
                    v3 = (v3 > 0.f) ? v3 : expm1f(v3);
                } else {
                    v2 = acc[mi][ni][2] + b0;
                    v3 = acc[mi][ni][3] + b1;
                }
                *reinterpret_cast<float2*>(&C[rB * ldc + col]) = make_float2(v2, v3);
            }
        }
    }
}

// ---------------- fused GRU: gi+gh GEMMs + gates + relu ----------------
__device__ __forceinline__ float sigm(float x) { return 1.f / (1.f + __expf(-x)); }

#define GRU_AST 20
#define GRU_BST 392
#define GRU_ASZ (64 * GRU_AST)
#define GRU_BSZ (16 * GRU_BST)
#define GRU_SMEM ((2 * GRU_ASZ + 2 * GRU_BSZ) * 4)   // 60416 bytes

__global__ __launch_bounds__(256)
void k_gru(const float* __restrict__ ctx, const float* __restrict__ h,
           const float* __restrict__ Wih, const float* __restrict__ Whh,
           const float* __restrict__ bih, const float* __restrict__ bhh,
           float* __restrict__ out, int M) {
    extern __shared__ unsigned smu[];
    unsigned* Cs = smu;
    unsigned* Hs = smu + GRU_ASZ;
    unsigned* Bi = smu + 2 * GRU_ASZ;
    unsigned* Bh = Bi + GRU_BSZ;

    const int t = threadIdx.x;
    const int lane = t & 31;
    const int warp = t >> 5;
    const int warpM = warp >> 1;
    const int warpN = warp & 1;
    const int row0 = blockIdx.x * 64;

    float accA[8][4], accB[8][4], accC[8][4], accD[8][4];
#pragma unroll
    for (int f = 0; f < 8; f++)
#pragma unroll
        for (int q = 0; q < 4; q++) {
            accA[f][q] = 0.f; accB[f][q] = 0.f;
            accC[f][q] = 0.f; accD[f][q] = 0.f;
        }

    const int ar = lane >> 2, ac = lane & 3;
    const int bk = lane & 3, bn = lane >> 2;

    const int arow = t >> 2;
    const int acol = (t & 3) << 2;
    float4 rc, rh, rbi[6], rbh[6];

    auto load_regs = [&](int s) {
        int k0 = s * 16;
        int grow = row0 + arow;
        if (grow < M) {
            rc = *reinterpret_cast<const float4*>(ctx + grow * 128 + k0 + acol);
            rh = *reinterpret_cast<const float4*>(h + grow * 128 + k0 + acol);
        } else {
            rc = make_float4(0, 0, 0, 0);
            rh = make_float4(0, 0, 0, 0);
        }
#pragma unroll
        for (int i = 0; i < 6; i++) {
            int lin = t + i * 256;
            int kr = lin / 96;
            int nn = (lin % 96) << 2;
            rbi[i] = *reinterpret_cast<const float4*>(Wih + (k0 + kr) * 384 + nn);
            rbh[i] = *reinterpret_cast<const float4*>(Whh + (k0 + kr) * 384 + nn);
        }
    };

    auto store_stage = [&]() {
        unsigned* c = Cs + arow * GRU_AST + acol;
        c[0] = f2tf(rc.x); c[1] = f2tf(rc.y); c[2] = f2tf(rc.z); c[3] = f2tf(rc.w);
        unsigned* hh = Hs + arow * GRU_AST + acol;
        hh[0] = f2tf(rh.x); hh[1] = f2tf(rh.y); hh[2] = f2tf(rh.z); hh[3] = f2tf(rh.w);
#pragma unroll
        for (int i = 0; i < 6; i++) {
            int lin = t + i * 256;
            int kr = lin / 96;
            int nn = (lin % 96) << 2;
            unsigned* bi = Bi + kr * GRU_BST + nn;
            bi[0] = f2tf(rbi[i].x); bi[1] = f2tf(rbi[i].y);
            bi[2] = f2tf(rbi[i].z); bi[3] = f2tf(rbi[i].w);
            unsigned* bh = Bh + kr * GRU_BST + nn;
            bh[0] = f2tf(rbh[i].x); bh[1] = f2tf(rbh[i].y);
            bh[2] = f2tf(rbh[i].z); bh[3] = f2tf(rbh[i].w);
        }
    };

    load_regs(0);

    for (int s = 0; s < 8; s++) {
        __syncthreads();
        store_stage();
        if (s + 1 < 8) load_regs(s + 1);
        __syncthreads();

#pragma unroll
        for (int kk = 0; kk < 16; kk += 8) {
            unsigned afc[4], afh[4];
            {
                int rb = warpM * 16;
                afc[0] = Cs[(rb + ar) * GRU_AST + kk + ac];
                afc[1] = Cs[(rb + ar + 8) * GRU_AST + kk + ac];
                afc[2] = Cs[(rb + ar) * GRU_AST + kk + ac + 4];
                afc[3] = Cs[(rb + ar + 8) * GRU_AST + kk + ac + 4];
                afh[0] = Hs[(rb + ar) * GRU_AST + kk + ac];
                afh[1] = Hs[(rb + ar + 8) * GRU_AST + kk + ac];
                afh[2] = Hs[(rb + ar) * GRU_AST + kk + ac + 4];
                afh[3] = Hs[(rb + ar + 8) * GRU_AST + kk + ac + 4];
            }
#pragma unroll
            for (int f = 0; f < 8; f++) {
                int nbr = 0 + warpN * 64 + f * 8;
                int nbz = 128 + warpN * 64 + f * 8;
                int nbn = 256 + warpN * 64 + f * 8;
                unsigned bir0 = Bi[(kk + bk) * GRU_BST + nbr + bn];
                unsigned bir1 = Bi[(kk + bk + 4) * GRU_BST + nbr + bn];
                unsigned bhr0 = Bh[(kk + bk) * GRU_BST + nbr + bn];
                unsigned bhr1 = Bh[(kk + bk + 4) * GRU_BST + nbr + bn];
                unsigned biz0 = Bi[(kk + bk) * GRU_BST + nbz + bn];
                unsigned biz1 = Bi[(kk + bk + 4) * GRU_BST + nbz + bn];
                unsigned bhz0 = Bh[(kk + bk) * GRU_BST + nbz + bn];
                unsigned bhz1 = Bh[(kk + bk + 4) * GRU_BST + nbz + bn];
                unsigned bin0 = Bi[(kk + bk) * GRU_BST + nbn + bn];
                unsigned bin1 = Bi[(kk + bk + 4) * GRU_BST + nbn + bn];
                unsigned bhn0 = Bh[(kk + bk) * GRU_BST + nbn + bn];
                unsigned bhn1 = Bh[(kk + bk + 4) * GRU_BST + nbn + bn];
                MMA_TF32(accA[f], afc[0], afc[1], afc[2], afc[3], bir0, bir1);
                MMA_TF32(accA[f], afh[0], afh[1], afh[2], afh[3], bhr0, bhr1);
                MMA_TF32(accB[f], afc[0], afc[1], afc[2], afc[3], biz0, biz1);
                MMA_TF32(accB[f], afh[0], afh[1], afh[2], afh[3], bhz0, bhz1);
                MMA_TF32(accC[f], afc[0], afc[1], afc[2], afc[3], bin0, bin1);
                MMA_TF32(accD[f], afh[0], afh[1], afh[2], afh[3], bhn0, bhn1);
            }
        }
    }

    // epilogue: gates + relu
    int rA = row0 + warpM * 16 + (lane >> 2);
    int rB = rA + 8;
#pragma unroll
    for (int f = 0; f < 8; f++) {
        int i0 = warpN * 64 + f * 8 + (lane & 3) * 2;
        float2 bi_r = *reinterpret_cast<const float2*>(&bih[i0]);
        float2 bi_z = *reinterpret_cast<const float2*>(&bih[128 + i0]);
        float2 bi_n = *reinterpret_cast<const float2*>(&bih[256 + i0]);
        float2 bh_r = *reinterpret_cast<const float2*>(&bhh[i0]);
        float2 bh_z = *reinterpret_cast<const float2*>(&bhh[128 + i0]);
        float2 bh_n = *reinterpret_cast<const float2*>(&bhh[256 + i0]);
#pragma unroll
        for (int half = 0; half < 2; half++) {
            int row = half ? rB : rA;
            int q = half * 2;
            if (row >= M) continue;
            float2 hv = *reinterpret_cast<const float2*>(&h[row * 128 + i0]);
            float r0 = sigm(accA[f][q]     + bi_r.x + bh_r.x);
            float r1 = sigm(accA[f][q + 1] + bi_r.y + bh_r.y);
            float z0 = sigm(accB[f][q]     + bi_z.x + bh_z.x);
            float z1 = sigm(accB[f][q + 1] + bi_z.y + bh_z.y);
            float n0 = tanhf(accC[f][q]     + bi_n.x + r0 * (accD[f][q]     + bh_n.x));
            float n1 = tanhf(accC[f][q + 1] + bi_n.y + r1 * (accD[f][q + 1] + bh_n.y));
            float o0 = fmaxf((1.f - z0) * n0 + z0 * hv.x, 0.f);
            float o1 = fmaxf((1.f - z1) * n1 + z1 * hv.y, 0.f);
            *reinterpret_cast<float2*>(&out[row * 128 + i0]) = make_float2(o0, o1);
        }
    }
}

// ---------------- launch ----------------
extern "C" void kernel_launch(void* const* d_in, const int* in_sizes, int n_in,
                              void* d_out, int out_size) {
    const int*   dst = (const int*)d_in[0];
    const float* l1  = (const float*)d_in[1];
    const float* l2  = (const float*)d_in[2];
    const float* l3  = (const float*)d_in[3];
    const float* ef1 = (const float*)d_in[4];
    const float* ef2 = (const float*)d_in[5];
    const float* ef3 = (const float*)d_in[6];
    const float* nf1 = (const float*)d_in[7];
    const float* nf2 = (const float*)d_in[8];
    const float* nf3 = (const float*)d_in[9];
    const float* W1  = (const float*)d_in[10];
    const float* b1  = (const float*)d_in[11];
    const float* W2  = (const float*)d_in[12];
    const float* b2  = (const float*)d_in[13];
    const float* W3  = (const float*)d_in[14];
    const float* b3  = (const float*)d_in[15];
    const float* Wa  = (const float*)d_in[16];
    const float* ba  = (const float*)d_in[17];
    const float* Wn  = (const float*)d_in[18];
    const float* bn  = (const float*)d_in[19];
    const float* Wih = (const float*)d_in[20];
    const float* bih = (const float*)d_in[21];
    const float* Whh = (const float*)d_in[22];
    const float* bhh = (const float*)d_in[23];

    const int E = in_sizes[0];
    const int N = in_sizes[7] / 128;

    float *p_agg, *p_c, *p_ctx, *p_h, *p_s0, *p_s1, *p_s2;
    cudaGetSymbolAddress((void**)&p_agg, g_agg);
    cudaGetSymbolAddress((void**)&p_c, g_c);
    cudaGetSymbolAddress((void**)&p_ctx, g_ctx);
    cudaGetSymbolAddress((void**)&p_h, g_h);
    cudaGetSymbolAddress((void**)&p_s0, g_ssum0);
    cudaGetSymbolAddress((void**)&p_s1, g_ssum1);
    cudaGetSymbolAddress((void**)&p_s2, g_ssum2);

    const int nch = (N + 1023) / 1024;
    const int mtiles = (N + 127) / 128;

    cudaFuncSetAttribute(gemm_tc<384, 0, true>,
                         cudaFuncAttributeMaxDynamicSharedMemorySize, GEMM_SMEM);
    cudaFuncSetAttribute(gemm_tc<128, 1, false>,
                         cudaFuncAttributeMaxDynamicSharedMemorySize, GEMM_SMEM);
    cudaFuncSetAttribute(gemm_tc<384, 0, false>,
                         cudaFuncAttributeMaxDynamicSharedMemorySize, GEMM_SMEM);
    cudaFuncSetAttribute(k_gru,
                         cudaFuncAttributeMaxDynamicSharedMemorySize, GRU_SMEM);

    // exactly ONE side stream (two leaked pool memory past teardown in R7).
    // stream/events created per call, not destroyed: kernel_launch only
    // executes for correctness + capture.
    cudaStream_t s1;
    cudaStreamCreateWithFlags(&s1, cudaStreamNonBlocking);
    cudaEvent_t evF, evJ;
    cudaEventCreateWithFlags(&evF, cudaEventDisableTiming);
    cudaEventCreateWithFlags(&evJ, cudaEventDisableTiming);

    // fork s1: G2b = [nf1,nf2,nf3] @ Wn + bn (input-only dependency)
    cudaEventRecord(evF, 0);
    cudaStreamWaitEvent(s1, evF, 0);
    gemm_tc<384, 0, true><<<dim3(mtiles, 1, 1), 256, GEMM_SMEM, s1>>>(
        TriC{nf1, nf1, nf1}, nf2, nf3, 128, TriC{Wn, Wn, Wn}, 128,
        TriC{bn, bn, bn}, TriC{nullptr, nullptr, nullptr},
        TriO{p_h, p_h, p_h}, 128, N);
    cudaEventRecord(evJ, s1);

    // main stream: edge pipeline (init, edge1, fused scan, edge2, gather)
    k_init<<<(N + 255) / 256, 256>>>(N);
    k_edge1<<<(E + 255) / 256, 256>>>(dst, l1, l2, l3, E);
    k_scan<<<nch, 1024>>>(N, E);
    k_edge2<<<(E + 255) / 256, 256>>>(dst, l1, l2, l3, E);
    k_gather<<<(N + 7) / 8, 256>>>((const float4*)ef1, (const float4*)ef2,
                                   (const float4*)ef3, N);

    // G1 batched: c_j = elu(agg_j @ W_j + b_j * flag_j), j=0..2 via grid.z
    gemm_tc<128, 1, false><<<dim3(mtiles, 1, 3), 256, GEMM_SMEM>>>(
        TriC{p_agg, p_agg + 128, p_agg + 256}, nullptr, nullptr, 384,
        TriC{W1, W2, W3}, 128, TriC{b1, b2, b3}, TriC{p_s0, p_s1, p_s2},
        TriO{p_c, p_c + 128, p_c + 256}, 384, N);

    // G2a: ctx = c @ Wa + ba
    gemm_tc<384, 0, false><<<dim3(mtiles, 1, 1), 256, GEMM_SMEM>>>(
        TriC{p_c, nullptr, nullptr}, nullptr, nullptr, 384,
        TriC{Wa, nullptr, nullptr}, 128, TriC{ba, nullptr, nullptr},
        TriC{nullptr, nullptr, nullptr}, TriO{p_ctx, nullptr, nullptr}, 128, N);

    // join G2b, then fused GRU (gi-GEMM + gh-GEMM + gates + relu)
    cudaStreamWaitEvent(0, evJ, 0);
    k_gru<<<(N + 63) / 64, 256, GRU_SMEM>>>(p_ctx, p_h, Wih, Whh, bih, bhh,
                                            (float*)d_out, N);
}

// round 17
// speedup vs baseline: 1.0315x; 1.0315x over previous
#include <cuda_runtime.h>
#include <cuda_bf16.h>
#include <math.h>

// Problem constants (fixed-shape problem)
#define NMAX 50048
#define EMAX 800000

// ---------------- device scratch (no allocations allowed) ----------------
__device__ int    g_cnt[NMAX];
__device__ int    g_rowptr[NMAX + 2];
__device__ int    g_wcur[NMAX];
__device__ int    g_eid[EMAX];
__device__ float4 g_wp[EMAX];          // normalized (w0,w1,w2,0) in CSR order
__device__ float  g_ssum0[NMAX];       // after scan3: holds 1/sum (or 0)
__device__ float  g_ssum1[NMAX];
__device__ float  g_ssum2[NMAX];
__device__ float  g_agg[50000 * 384];
__device__ float  g_c[50000 * 384];
__device__ float  g_ctx[50000 * 128];
__device__ float  g_h[50000 * 128];
__device__ int    g_chunk[64];

// ---------------- small helpers ----------------
__device__ __forceinline__ unsigned f2tf(float x) {
    unsigned r;
    asm("cvt.rna.tf32.f32 %0, %1;" : "=r"(r) : "f"(x));
    return r;
}
__device__ __forceinline__ unsigned s2u(const void* p) {
    unsigned r;
    asm("{ .reg .u64 t; cvta.to.shared.u64 t, %1; cvt.u32.u64 %0, t; }"
        : "=r"(r) : "l"(p));
    return r;
}
#define CP16(dst, src, sz) \
    asm volatile("cp.async.cg.shared.global [%0], [%1], 16, %2;" \
                 :: "r"(dst), "l"(src), "r"(sz))
#define CPCOMMIT() asm volatile("cp.async.commit_group;")
#define CPWAIT(n)  asm volatile("cp.async.wait_group %0;" :: "n"(n))
#define MMA_TF32(acc, a0, a1, a2, a3, b0, b1) \
    asm volatile( \
        "mma.sync.aligned.m16n8k8.row.col.f32.tf32.tf32.f32 " \
        "{%0,%1,%2,%3}, {%4,%5,%6,%7}, {%8,%9}, {%0,%1,%2,%3};" \
        : "+f"((acc)[0]), "+f"((acc)[1]), "+f"((acc)[2]), "+f"((acc)[3]) \
        : "r"(a0), "r"(a1), "r"(a2), "r"(a3), "r"(b0), "r"(b1))

// ---------------- init ----------------
__global__ void k_init(int N) {
    int i = blockIdx.x * blockDim.x + threadIdx.x;
    if (i < N) {
        g_cnt[i] = 0;
        g_ssum0[i] = 0.f; g_ssum1[i] = 0.f; g_ssum2[i] = 0.f;
    }
}

// ---------------- edge pass 1: histogram + exp-sums ----------------
__global__ void k_edge1(const int* __restrict__ dst,
                        const float* __restrict__ l1,
                        const float* __restrict__ l2,
                        const float* __restrict__ l3, int E) {
    int e = blockIdx.x * blockDim.x + threadIdx.x;
    if (e >= E) return;
    int d = dst[e];
    atomicAdd(&g_cnt[d], 1);
    atomicAdd(&g_ssum0[d], __expf(l1[e]));
    atomicAdd(&g_ssum1[d], __expf(l2[e]));
    atomicAdd(&g_ssum2[d], __expf(l3[e]));
}

// ---------------- scan kernel 1: per-chunk inclusive prefix (warp shuffles) ---
__global__ void k_scan1(int N) {
    __shared__ int wsum[32];
    int t = threadIdx.x;
    int lane = t & 31;
    int w = t >> 5;
    int n = blockIdx.x * 1024 + t;
    int v = (n < N) ? g_cnt[n] : 0;
    // warp inclusive scan
    int x = v;
#pragma unroll
    for (int off = 1; off < 32; off <<= 1) {
        int y = __shfl_up_sync(0xffffffffu, x, off);
        if (lane >= off) x += y;
    }
    if (lane == 31) wsum[w] = x;
    __syncthreads();
    // warp 0 scans the 32 warp totals
    if (w == 0) {
        int s = wsum[lane];
#pragma unroll
        for (int off = 1; off < 32; off <<= 1) {
            int y = __shfl_up_sync(0xffffffffu, s, off);
            if (lane >= off) s += y;
        }
        wsum[lane] = s;
    }
    __syncthreads();
    int incl = x + ((w > 0) ? wsum[w - 1] : 0);
    if (n < N) g_rowptr[n] = incl - v;          // exclusive within chunk
    if (t == 1023) g_chunk[blockIdx.x] = incl;  // chunk total
}

// ---------------- scan kernel 2: add chunk offsets + invert sums -------------
__global__ void k_scan3(int N, int E) {
    __shared__ int off_sh;
    if (threadIdx.x == 0) {
        int run = 0;
        for (int i = 0; i < (int)blockIdx.x; i++) run += g_chunk[i];
        off_sh = run;
    }
    __syncthreads();
    int n = blockIdx.x * 1024 + threadIdx.x;
    if (n < N) {
        int v = g_rowptr[n] + off_sh;
        g_rowptr[n] = v;
        g_wcur[n] = v;
        float s0 = g_ssum0[n]; g_ssum0[n] = (s0 > 0.f) ? 1.f / s0 : 0.f;
        float s1 = g_ssum1[n]; g_ssum1[n] = (s1 > 0.f) ? 1.f / s1 : 0.f;
        float s2 = g_ssum2[n]; g_ssum2[n] = (s2 > 0.f) ? 1.f / s2 : 0.f;
    }
    if (n == 0) g_rowptr[N] = E;
}

// ---------------- edge pass 2: scatter edge ids + normalized packed weights ----
__global__ void k_edge2(const int* __restrict__ dst,
                        const float* __restrict__ l1,
                        const float* __restrict__ l2,
                        const float* __restrict__ l3, int E) {
    int e = blockIdx.x * blockDim.x + threadIdx.x;
    if (e >= E) return;
    int d = dst[e];
    int p = atomicAdd(&g_wcur[d], 1);
    g_eid[p] = e;
    float4 w;
    w.x = __expf(l1[e]) * g_ssum0[d];
    w.y = __expf(l2[e]) * g_ssum1[d];
    w.z = __expf(l3[e]) * g_ssum2[d];
    w.w = 0.f;
    g_wp[p] = w;
}

// ---------------- gather: agg_i[n] = sum_e a_i(e) * ef_i[e] ----------------
__global__ void k_gather(const float4* __restrict__ ef1,
                         const float4* __restrict__ ef2,
                         const float4* __restrict__ ef3, int N) {
    int warp = blockIdx.x * 8 + (threadIdx.x >> 5);
    int lane = threadIdx.x & 31;
    if (warp >= N) return;
    int s = g_rowptr[warp];
    int eend = g_rowptr[warp + 1];
    float4 a0 = {0, 0, 0, 0}, a1 = {0, 0, 0, 0}, a2 = {0, 0, 0, 0};
    int k = s;
    for (; k + 4 <= eend; k += 4) {
        int e0 = g_eid[k], e1 = g_eid[k + 1], e2 = g_eid[k + 2], e3 = g_eid[k + 3];
        float4 wA = g_wp[k], wB = g_wp[k + 1], wC = g_wp[k + 2], wD = g_wp[k + 3];
        float4 u0 = ef1[e0 * 32 + lane], u1 = ef1[e1 * 32 + lane];
        float4 u2 = ef1[e2 * 32 + lane], u3 = ef1[e3 * 32 + lane];
        float4 v0 = ef2[e0 * 32 + lane], v1 = ef2[e1 * 32 + lane];
        float4 v2 = ef2[e2 * 32 + lane], v3 = ef2[e3 * 32 + lane];
        float4 x0 = ef3[e0 * 32 + lane], x1 = ef3[e1 * 32 + lane];
        float4 x2 = ef3[e2 * 32 + lane], x3 = ef3[e3 * 32 + lane];
        a0.x += wA.x * u0.x + wB.x * u1.x + wC.x * u2.x + wD.x * u3.x;
        a0.y += wA.x * u0.y + wB.x * u1.y + wC.x * u2.y + wD.x * u3.y;
        a0.z += wA.x * u0.z + wB.x * u1.z + wC.x * u2.z + wD.x * u3.z;
        a0.w += wA.x * u0.w + wB.x * u1.w + wC.x * u2.w + wD.x * u3.w;
        a1.x += wA.y * v0.x + wB.y * v1.x + wC.y * v2.x + wD.y * v3.x;
        a1.y += wA.y * v0.y + wB.y * v1.y + wC.y * v2.y + wD.y * v3.y;
        a1.z += wA.y * v0.z + wB.y * v1.z + wC.y * v2.z + wD.y * v3.z;
        a1.w += wA.y * v0.w + wB.y * v1.w + wC.y * v2.w + wD.y * v3.w;
        a2.x += wA.z * x0.x + wB.z * x1.x + wC.z * x2.x + wD.z * x3.x;
        a2.y += wA.z * x0.y + wB.z * x1.y + wC.z * x2.y + wD.z * x3.y;
        a2.z += wA.z * x0.z + wB.z * x1.z + wC.z * x2.z + wD.z * x3.z;
        a2.w += wA.z * x0.w + wB.z * x1.w + wC.z * x2.w + wD.z * x3.w;
    }
    for (; k < eend; k++) {
        int e = g_eid[k];
        float4 w = g_wp[k];
        float4 u = ef1[e * 32 + lane];
        float4 v = ef2[e * 32 + lane];
        float4 x = ef3[e * 32 + lane];
        a0.x += w.x * u.x; a0.y += w.x * u.y; a0.z += w.x * u.z; a0.w += w.x * u.w;
        a1.x += w.y * v.x; a1.y += w.y * v.y; a1.z += w.y * v.z; a1.w += w.y * v.w;
        a2.x += w.z * x.x; a2.y += w.z * x.y; a2.z += w.z * x.z; a2.w += w.z * x.w;
    }
    float4* out = reinterpret_cast<float4*>(g_agg) + warp * 96;
    out[lane]      = a0;
    out[32 + lane] = a1;
    out[64 + lane] = a2;
}

// ---------------- TF32 tensor-core GEMM (cp.async 3-stage pipelined) ----------------
struct TriC { const float* p0; const float* p1; const float* p2; };
struct TriO { float* p0; float* p1; float* p2; };
__device__ __forceinline__ const float* sel(const TriC& t, int z) {
    return z == 0 ? t.p0 : (z == 1 ? t.p1 : t.p2);
}
__device__ __forceinline__ float* sel(const TriO& t, int z) {
    return z == 0 ? t.p0 : (z == 1 ? t.p1 : t.p2);
}

#define GEMM_ASZ (128 * 36)
#define GEMM_BSZ (32 * 136)
#define GEMM_STAGE (GEMM_ASZ + GEMM_BSZ)
#define GEMM_SMEM (3 * GEMM_STAGE * 4)

template <int KTOT, int EPI, bool CONCAT3>
__global__ __launch_bounds__(256, 2)
void gemm_tc(TriC a0t, const float* __restrict__ A1, const float* __restrict__ A2,
             int lda, TriC bt, int ldb, TriC biast, TriC flagt,
             TriO ct, int ldc, int M) {
    extern __shared__ float smem[];
    const int z = blockIdx.z;
    const float* __restrict__ A0 = sel(a0t, z);
    const float* __restrict__ B = sel(bt, z);
    const float* __restrict__ bias = sel(biast, z);
    const float* __restrict__ flag_s = sel(flagt, z);
    float* __restrict__ C = sel(ct, z);

    const int t = threadIdx.x;
    const int lane = t & 31;
    const int warp = t >> 5;
    const int warpM = warp >> 1;
    const int warpN = warp & 1;
    const int row0 = blockIdx.x * 128;
    const int coff = blockIdx.y * 128;

    float acc[2][8][4];
#pragma unroll
    for (int i = 0; i < 2; i++)
#pragma unroll
        for (int j = 0; j < 8; j++)
#pragma unroll
            for (int q = 0; q < 4; q++) acc[i][j][q] = 0.f;

    const int ar = lane >> 2, ac = lane & 3;
    const int bk = lane & 3, bn = lane >> 2;
    const int NKB = KTOT / 32;

    auto issue_tile = [&](int kb) {
        float* stage = smem + (kb % 3) * GEMM_STAGE;
        float* As = stage;
        float* Bs = stage + GEMM_ASZ;
        int k0 = kb * 32;
#pragma unroll
        for (int i = 0; i < 4; i++) {
            int lin = t + i * 256;
            int r = lin >> 3;
            int kk = (lin & 7) << 2;
            int grow = row0 + r;
            bool ok = grow < M;
            const float* src;
            int kg = k0 + kk;
            if (CONCAT3) {
                const float* Ap = (kg < 128) ? A0 : ((kg < 256) ? A1 : A2);
                src = ok ? (Ap + grow * 128 + (kg & 127)) : A0;
            } else {
                src = ok ? (A0 + grow * lda + kg) : A0;
            }
            CP16(s2u(As + r * 36 + kk), src, ok ? 16 : 0);
        }
#pragma unroll
        for (int i = 0; i < 4; i++) {
            int lin = t + i * 256;
            int kr = lin >> 5;
            int nn = (lin & 31) << 2;
            CP16(s2u(Bs + kr * 136 + nn), B + (k0 + kr) * ldb + coff + nn, 16);
        }
    };

    issue_tile(0); CPCOMMIT();
    if (NKB > 1) { issue_tile(1); CPCOMMIT(); }

    for (int kb = 0; kb < NKB; kb++) {
        if (kb + 1 < NKB) { CPWAIT(1); } else { CPWAIT(0); }
        __syncthreads();
        if (kb + 2 < NKB) { issue_tile(kb + 2); CPCOMMIT(); }

        float* stage = smem + (kb % 3) * GEMM_STAGE;
        float* As = stage;
        float* Bs = stage + GEMM_ASZ;
#pragma unroll
        for (int kk = 0; kk < 32; kk += 8) {
            unsigned af[2][4];
#pragma unroll
            for (int mi = 0; mi < 2; mi++) {
                int rb = warpM * 32 + mi * 16;
                af[mi][0] = f2tf(As[(rb + ar) * 36 + kk + ac]);
                af[mi][1] = f2tf(As[(rb + ar + 8) * 36 + kk + ac]);
                af[mi][2] = f2tf(As[(rb + ar) * 36 + kk + ac + 4]);
                af[mi][3] = f2tf(As[(rb + ar + 8) * 36 + kk + ac + 4]);
            }
            unsigned bf[8][2];
#pragma unroll
            for (int ni = 0; ni < 8; ni++) {
                int nb = warpN * 64 + ni * 8;
                bf[ni][0] = f2tf(Bs[(kk + bk) * 136 + nb + bn]);
                bf[ni][1] = f2tf(Bs[(kk + bk + 4) * 136 + nb + bn]);
            }
#pragma unroll
            for (int mi = 0; mi < 2; mi++)
#pragma unroll
                for (int ni = 0; ni < 8; ni++)
                    MMA_TF32(acc[mi][ni], af[mi][0], af[mi][1], af[mi][2],
                             af[mi][3], bf[ni][0], bf[ni][1]);
        }
    }

#pragma unroll
    for (int mi = 0; mi < 2; mi++) {
        int rA = row0 + warpM * 32 + mi * 16 + (lane >> 2);
        int rB = rA + 8;
        float flA = 1.f, flB = 1.f;
        if (EPI == 1) {
            flA = (rA < M && flag_s[rA] > 0.f) ? 1.f : 0.f;
            flB = (rB < M && flag_s[rB] > 0.f) ? 1.f : 0.f;
        }
#pragma unroll
        for (int ni = 0; ni < 8; ni++) {
            int col = coff + warpN * 64 + ni * 8 + (lane & 3) * 2;
            float b0 = bias[col], b1 = bias[col + 1];
            if (rA < M) {
                float v0, v1;
                if (EPI == 1) {
                    v0 = acc[mi][ni][0] + b0 * flA;
                    v1 = acc[mi][ni][1] + b1 * flA;
                    v0 = (v0 > 0.f) ? v0 : expm1f(v0);
                    v1 = (v1 > 0.f) ? v1 : expm1f(v1);
                } else {
                    v0 = acc[mi][ni][0] + b0;
                    v1 = acc[mi][ni][1] + b1;
                }
                *reinterpret_cast<float2*>(&C[rA * ldc + col]) = make_float2(v0, v1);
            }
            if (rB < M) {
                float v2, v3;
                if (EPI == 1) {
                    v2 = acc[mi][ni][2] + b0 * flB;
                    v3 = acc[mi][ni][3] + b1 * flB;
                    v2 = (v2 > 0.f) ? v2 : expm1f(v2);
                    v3 = (v3 > 0.f) ? v3 : expm1f(v3);
                } else {
                    v2 = acc[mi][ni][2] + b0;
                    v3 = acc[mi][ni][3] + b1;
                }
                *reinterpret_cast<float2*>(&C[rB * ldc + col]) = make_float2(v2, v3);
            }
        }
    }
}

// ---------------- fused GRU: gi+gh GEMMs + gates + relu ----------------
__device__ __forceinline__ float sigm(float x) { return 1.f / (1.f + __expf(-x)); }

#define GRU_AST 20
#define GRU_BST 392
#define GRU_ASZ (64 * GRU_AST)
#define GRU_BSZ (16 * GRU_BST)
#define GRU_SMEM ((2 * GRU_ASZ + 2 * GRU_BSZ) * 4)   // 60416 bytes

__global__ __launch_bounds__(256)
void k_gru(const float* __restrict__ ctx, const float* __restrict__ h,
           const float* __restrict__ Wih, const float* __restrict__ Whh,
           const float* __restrict__ bih, const float* __restrict__ bhh,
           float* __restrict__ out, int M) {
    extern __shared__ unsigned smu[];
    unsigned* Cs = smu;
    unsigned* Hs = smu + GRU_ASZ;
    unsigned* Bi = smu + 2 * GRU_ASZ;
    unsigned* Bh = Bi + GRU_BSZ;

    const int t = threadIdx.x;
    const int lane = t & 31;
    const int warp = t >> 5;
    const int warpM = warp >> 1;
    const int warpN = warp & 1;
    const int row0 = blockIdx.x * 64;

    float accA[8][4], accB[8][4], accC[8][4], accD[8][4];
#pragma unroll
    for (int f = 0; f < 8; f++)
#pragma unroll
        for (int q = 0; q < 4; q++) {
            accA[f][q] = 0.f; accB[f][q] = 0.f;
            accC[f][q] = 0.f; accD[f][q] = 0.f;
        }

    const int ar = lane >> 2, ac = lane & 3;
    const int bk = lane & 3, bn = lane >> 2;

    const int arow = t >> 2;
    const int acol = (t & 3) << 2;
    float4 rc, rh, rbi[6], rbh[6];

    auto load_regs = [&](int s) {
        int k0 = s * 16;
        int grow = row0 + arow;
        if (grow < M) {
            rc = *reinterpret_cast<const float4*>(ctx + grow * 128 + k0 + acol);
            rh = *reinterpret_cast<const float4*>(h + grow * 128 + k0 + acol);
        } else {
            rc = make_float4(0, 0, 0, 0);
            rh = make_float4(0, 0, 0, 0);
        }
#pragma unroll
        for (int i = 0; i < 6; i++) {
            int lin = t + i * 256;
            int kr = lin / 96;
            int nn = (lin % 96) << 2;
            rbi[i] = *reinterpret_cast<const float4*>(Wih + (k0 + kr) * 384 + nn);
            rbh[i] = *reinterpret_cast<const float4*>(Whh + (k0 + kr) * 384 + nn);
        }
    };

    auto store_stage = [&]() {
        unsigned* c = Cs + arow * GRU_AST + acol;
        c[0] = f2tf(rc.x); c[1] = f2tf(rc.y); c[2] = f2tf(rc.z); c[3] = f2tf(rc.w);
        unsigned* hh = Hs + arow * GRU_AST + acol;
        hh[0] = f2tf(rh.x); hh[1] = f2tf(rh.y); hh[2] = f2tf(rh.z); hh[3] = f2tf(rh.w);
#pragma unroll
        for (int i = 0; i < 6; i++) {
            int lin = t + i * 256;
            int kr = lin / 96;
            int nn = (lin % 96) << 2;
            unsigned* bi = Bi + kr * GRU_BST + nn;
            bi[0] = f2tf(rbi[i].x); bi[1] = f2tf(rbi[i].y);
            bi[2] = f2tf(rbi[i].z); bi[3] = f2tf(rbi[i].w);
            unsigned* bh = Bh + kr * GRU_BST + nn;
            bh[0] = f2tf(rbh[i].x); bh[1] = f2tf(rbh[i].y);
            bh[2] = f2tf(rbh[i].z); bh[3] = f2tf(rbh[i].w);
        }
    };

    load_regs(0);

    for (int s = 0; s < 8; s++) {
        __syncthreads();
        store_stage();
        if (s + 1 < 8) load_regs(s + 1);
        __syncthreads();

#pragma unroll
        for (int kk = 0; kk < 16; kk += 8) {
            unsigned afc[4], afh[4];
            {
                int rb = warpM * 16;
                afc[0] = Cs[(rb + ar) * GRU_AST + kk + ac];
                afc[1] = Cs[(rb + ar + 8) * GRU_AST + kk + ac];
                afc[2] = Cs[(rb + ar) * GRU_AST + kk + ac + 4];
                afc[3] = Cs[(rb + ar + 8) * GRU_AST + kk + ac + 4];
                afh[0] = Hs[(rb + ar) * GRU_AST + kk + ac];
                afh[1] = Hs[(rb + ar + 8) * GRU_AST + kk + ac];
                afh[2] = Hs[(rb + ar) * GRU_AST + kk + ac + 4];
                afh[3] = Hs[(rb + ar + 8) * GRU_AST + kk + ac + 4];
            }
#pragma unroll
            for (int f = 0; f < 8; f++) {
                int nbr = 0 + warpN * 64 + f * 8;
                int nbz = 128 + warpN * 64 + f * 8;
                int nbn = 256 + warpN * 64 + f * 8;
                unsigned bir0 = Bi[(kk + bk) * GRU_BST + nbr + bn];
                unsigned bir1 = Bi[(kk + bk + 4) * GRU_BST + nbr + bn];
                unsigned bhr0 = Bh[(kk + bk) * GRU_BST + nbr + bn];
                unsigned bhr1 = Bh[(kk + bk + 4) * GRU_BST + nbr + bn];
                unsigned biz0 = Bi[(kk + bk) * GRU_BST + nbz + bn];
                unsigned biz1 = Bi[(kk + bk + 4) * GRU_BST + nbz + bn];
                unsigned bhz0 = Bh[(kk + bk) * GRU_BST + nbz + bn];
                unsigned bhz1 = Bh[(kk + bk + 4) * GRU_BST + nbz + bn];
                unsigned bin0 = Bi[(kk + bk) * GRU_BST + nbn + bn];
                unsigned bin1 = Bi[(kk + bk + 4) * GRU_BST + nbn + bn];
                unsigned bhn0 = Bh[(kk + bk) * GRU_BST + nbn + bn];
                unsigned bhn1 = Bh[(kk + bk + 4) * GRU_BST + nbn + bn];
                MMA_TF32(accA[f], afc[0], afc[1], afc[2], afc[3], bir0, bir1);
                MMA_TF32(accA[f], afh[0], afh[1], afh[2], afh[3], bhr0, bhr1);
                MMA_TF32(accB[f], afc[0], afc[1], afc[2], afc[3], biz0, biz1);
                MMA_TF32(accB[f], afh[0], afh[1], afh[2], afh[3], bhz0, bhz1);
                MMA_TF32(accC[f], afc[0], afc[1], afc[2], afc[3], bin0, bin1);
                MMA_TF32(accD[f], afh[0], afh[1], afh[2], afh[3], bhn0, bhn1);
            }
        }
    }

    // epilogue: gates + relu
    int rA = row0 + warpM * 16 + (lane >> 2);
    int rB = rA + 8;
#pragma unroll
    for (int f = 0; f < 8; f++) {
        int i0 = warpN * 64 + f * 8 + (lane & 3) * 2;
        float2 bi_r = *reinterpret_cast<const float2*>(&bih[i0]);
        float2 bi_z = *reinterpret_cast<const float2*>(&bih[128 + i0]);
        float2 bi_n = *reinterpret_cast<const float2*>(&bih[256 + i0]);
        float2 bh_r = *reinterpret_cast<const float2*>(&bhh[i0]);
        float2 bh_z = *reinterpret_cast<const float2*>(&bhh[128 + i0]);
        float2 bh_n = *reinterpret_cast<const float2*>(&bhh[256 + i0]);
#pragma unroll
        for (int half = 0; half < 2; half++) {
            int row = half ? rB : rA;
            int q = half * 2;
            if (row >= M) continue;
            float2 hv = *reinterpret_cast<const float2*>(&h[row * 128 + i0]);
            float r0 = sigm(accA[f][q]     + bi_r.x + bh_r.x);
            float r1 = sigm(accA[f][q + 1] + bi_r.y + bh_r.y);
            float z0 = sigm(accB[f][q]     + bi_z.x + bh_z.x);
            float z1 = sigm(accB[f][q + 1] + bi_z.y + bh_z.y);
            float n0 = tanhf(accC[f][q]     + bi_n.x + r0 * (accD[f][q]     + bh_n.x));
            float n1 = tanhf(accC[f][q + 1] + bi_n.y + r1 * (accD[f][q + 1] + bh_n.y));
            float o0 = fmaxf((1.f - z0) * n0 + z0 * hv.x, 0.f);
            float o1 = fmaxf((1.f - z1) * n1 + z1 * hv.y, 0.f);
            *reinterpret_cast<float2*>(&out[row * 128 + i0]) = make_float2(o0, o1);
        }
    }
}

// ---------------- launch ----------------
extern "C" void kernel_launch(void* const* d_in, const int* in_sizes, int n_in,
                              void* d_out, int out_size) {
    const int*   dst = (const int*)d_in[0];
    const float* l1  = (const float*)d_in[1];
    const float* l2  = (const float*)d_in[2];
    const float* l3  = (const float*)d_in[3];
    const float* ef1 = (const float*)d_in[4];
    const float* ef2 = (const float*)d_in[5];
    const float* ef3 = (const float*)d_in[6];
    const float* nf1 = (const float*)d_in[7];
    const float* nf2 = (const float*)d_in[8];
    const float* nf3 = (const float*)d_in[9];
    const float* W1  = (const float*)d_in[10];
    const float* b1  = (const float*)d_in[11];
    const float* W2  = (const float*)d_in[12];
    const float* b2  = (const float*)d_in[13];
    const float* W3  = (const float*)d_in[14];
    const float* b3  = (const float*)d_in[15];
    const float* Wa  = (const float*)d_in[16];
    const float* ba  = (const float*)d_in[17];
    const float* Wn  = (const float*)d_in[18];
    const float* bn  = (const float*)d_in[19];
    const float* Wih = (const float*)d_in[20];
    const float* bih = (const float*)d_in[21];
    const float* Whh = (const float*)d_in[22];
    const float* bhh = (const float*)d_in[23];

    const int E = in_sizes[0];
    const int N = in_sizes[7] / 128;

    float *p_agg, *p_c, *p_ctx, *p_h, *p_s0, *p_s1, *p_s2;
    cudaGetSymbolAddress((void**)&p_agg, g_agg);
    cudaGetSymbolAddress((void**)&p_c, g_c);
    cudaGetSymbolAddress((void**)&p_ctx, g_ctx);
    cudaGetSymbolAddress((void**)&p_h, g_h);
    cudaGetSymbolAddress((void**)&p_s0, g_ssum0);
    cudaGetSymbolAddress((void**)&p_s1, g_ssum1);
    cudaGetSymbolAddress((void**)&p_s2, g_ssum2);

    const int nch = (N + 1023) / 1024;
    const int mtiles = (N + 127) / 128;

    cudaFuncSetAttribute(gemm_tc<384, 0, true>,
                         cudaFuncAttributeMaxDynamicSharedMemorySize, GEMM_SMEM);
    cudaFuncSetAttribute(gemm_tc<128, 1, false>,
                         cudaFuncAttributeMaxDynamicSharedMemorySize, GEMM_SMEM);
    cudaFuncSetAttribute(gemm_tc<384, 0, false>,
                         cudaFuncAttributeMaxDynamicSharedMemorySize, GEMM_SMEM);
    cudaFuncSetAttribute(k_gru,
                         cudaFuncAttributeMaxDynamicSharedMemorySize, GRU_SMEM);

    // exactly ONE side stream (two leaked pool memory past teardown in R7).
    // stream/events created per call, not destroyed: kernel_launch only
    // executes for correctness + capture.
    cudaStream_t s1;
    cudaStreamCreateWithFlags(&s1, cudaStreamNonBlocking);
    cudaEvent_t evF, evJ;
    cudaEventCreateWithFlags(&evF, cudaEventDisableTiming);
    cudaEventCreateWithFlags(&evJ, cudaEventDisableTiming);

    // fork s1: G2b = [nf1,nf2,nf3] @ Wn + bn (input-only dependency)
    cudaEventRecord(evF, 0);
    cudaStreamWaitEvent(s1, evF, 0);
    gemm_tc<384, 0, true><<<dim3(mtiles, 1, 1), 256, GEMM_SMEM, s1>>>(
        TriC{nf1, nf1, nf1}, nf2, nf3, 128, TriC{Wn, Wn, Wn}, 128,
        TriC{bn, bn, bn}, TriC{nullptr, nullptr, nullptr},
        TriO{p_h, p_h, p_h}, 128, N);
    cudaEventRecord(evJ, s1);

    // main stream: edge pipeline
    k_init<<<(N + 255) / 256, 256>>>(N);
    k_edge1<<<(E + 255) / 256, 256>>>(dst, l1, l2, l3, E);
    k_scan1<<<nch, 1024>>>(N);
    k_scan3<<<nch, 1024>>>(N, E);
    k_edge2<<<(E + 255) / 256, 256>>>(dst, l1, l2, l3, E);
    k_gather<<<(N + 7) / 8, 256>>>((const float4*)ef1, (const float4*)ef2,
                                   (const float4*)ef3, N);

    // G1 batched: c_j = elu(agg_j @ W_j + b_j * flag_j), j=0..2 via grid.z
    gemm_tc<128, 1, false><<<dim3(mtiles, 1, 3), 256, GEMM_SMEM>>>(
        TriC{p_agg, p_agg + 128, p_agg + 256}, nullptr, nullptr, 384,
        TriC{W1, W2, W3}, 128, TriC{b1, b2, b3}, TriC{p_s0, p_s1, p_s2},
        TriO{p_c, p_c + 128, p_c + 256}, 384, N);

    // G2a: ctx = c @ Wa + ba
    gemm_tc<384, 0, false><<<dim3(mtiles, 1, 1), 256, GEMM_SMEM>>>(
        TriC{p_c, nullptr, nullptr}, nullptr, nullptr, 384,
        TriC{Wa, nullptr, nullptr}, 128, TriC{ba, nullptr, nullptr},
        TriC{nullptr, nullptr, nullptr}, TriO{p_ctx, nullptr, nullptr}, 128, N);

    // join G2b, then fused GRU (gi-GEMM + gh-GEMM + gates + relu)
    cudaStreamWaitEvent(0, evJ, 0);
    k_gru<<<(N + 63) / 64, 256, GRU_SMEM>>>(p_ctx, p_h, Wih, Whh, bih, bhh,
                                            (float*)d_out, N);
}